// round 10
// baseline (speedup 1.0000x reference)
#include <cuda_runtime.h>
#include <cstdint>

#define BATCH 16
#define HH 56
#define WW 56
#define NPIX (HH * WW)          // 3136
#define EPSV 1e-5f

// ---------------- device scratch (no allocation) ----------------
__device__ __align__(16) int8_t g_A1p[72 * 16 * 32 * 16];    // frag-packed w1 [chunk][m][lane][16B]
__device__ __align__(16) int8_t g_A2p[144 * 16 * 32 * 16];   // frag-packed w2 (shuffle-permuted k)
__device__ __align__(16) int8_t g_acts1[BATCH * 58 * 58 * 256];  // padded NHWC +-1
__device__ __align__(16) int8_t g_acts2[BATCH * 58 * 58 * 512];  // padded NHWC +-1
__device__ float g_xact[(size_t)BATCH * NPIX * 256];   // x[:, :256] NHWC (stage1 residual)
__device__ float g_idleb[(size_t)BATCH * NPIX * 256];  // x_idle + bias NHWC
__device__ float g_out1f[(size_t)BATCH * NPIX * 128];  // clipped out1 ch 0..127 NHWC
__device__ float g_alpha1[256], g_c1[256], g_alpha2[256], g_c2[256];

// ---------------- BN/scale prep ----------------
__global__ void prep_bn1(const float* __restrict__ w1, const float* __restrict__ gm,
                         const float* __restrict__ bt, const float* __restrict__ mn,
                         const float* __restrict__ vr) {
    int oc = blockIdx.x, c = threadIdx.x, lane = c & 31, wi = c >> 5;
    __shared__ float red[8];
    float asum = 0.f;
#pragma unroll
    for (int t = 0; t < 9; t++) asum += fabsf(w1[((size_t)(oc * 256 + c)) * 9 + t]);
    for (int o = 16; o > 0; o >>= 1) asum += __shfl_xor_sync(0xffffffffu, asum, o);
    if (lane == 0) red[wi] = asum;
    __syncthreads();
    if (c == 0) {
        float s = 0.f;
#pragma unroll
        for (int i = 0; i < 8; i++) s += red[i];
        float scale = s / (256.f * 9.f);
        float inv = gm[oc] / sqrtf(vr[oc] + EPSV);
        g_alpha1[oc] = scale * inv;
        g_c1[oc] = bt[oc] - mn[oc] * inv;
    }
}

__global__ void prep_bn2(const float* __restrict__ w2, const float* __restrict__ gm,
                         const float* __restrict__ bt, const float* __restrict__ mn,
                         const float* __restrict__ vr) {
    int oc = blockIdx.x, c = threadIdx.x, lane = c & 31, wi = c >> 5;
    __shared__ float red[8];
    float asum = 0.f;
    for (int it = 0; it < 2; it++) {
        int ic = it * 256 + c;
#pragma unroll
        for (int t = 0; t < 9; t++) asum += fabsf(w2[((size_t)(oc * 512 + ic)) * 9 + t]);
    }
    for (int o = 16; o > 0; o >>= 1) asum += __shfl_xor_sync(0xffffffffu, asum, o);
    if (lane == 0) red[wi] = asum;
    __syncthreads();
    if (c == 0) {
        float s = 0.f;
#pragma unroll
        for (int i = 0; i < 8; i++) s += red[i];
        float scale = s / (512.f * 9.f);
        float inv = gm[oc] / sqrtf(vr[oc] + EPSV);
        g_alpha2[oc] = scale * inv;
        g_c2[oc] = bt[oc] - mn[oc] * inv;
    }
}

// ---------------- fragment-packed weight binarization ----------------
// Layout: [chunk][m-frag 0..15][lane 0..31][16B], bytes 0-3=a0,4-7=a1,8-11=a2,12-15=a3.
// a0:(row=g,k=q*4+j) a1:(row+8) a2:(k+16) a3:(row+8,k+16); oc=m*16+row, ic=icc*32+k.
__global__ void pack_w1(const float* __restrict__ w1) {
    int c = blockIdx.x;             // chunk 0..71: tap=c>>3, icc=c&7
    int tid = threadIdx.x;          // 512
    int m = tid >> 5, lane = tid & 31;
    int tap = c >> 3, icc = c & 7;
    uint32_t words[4];
#pragma unroll
    for (int pair = 0; pair < 4; pair++) {
        int oc = m * 16 + (lane >> 2) + (pair & 1) * 8;
        int kk = (pair >> 1) * 16 + (lane & 3) * 4;
        uint32_t wd = 0;
#pragma unroll
        for (int j = 0; j < 4; j++) {
            int ic = icc * 32 + kk + j;
            float v = w1[((size_t)(oc * 256 + ic)) * 9 + tap];
            wd |= (uint32_t)(uint8_t)(int8_t)(v >= 0.f ? 1 : -1) << (8 * j);
        }
        words[pair] = wd;
    }
    *(uint4*)(g_A1p + ((size_t)(c * 16 + m) * 32 + lane) * 16) =
        make_uint4(words[0], words[1], words[2], words[3]);
}

__global__ void pack_w2(const float* __restrict__ w2) {
    int c = blockIdx.x;             // chunk 0..143: tap=c>>4, icc=c&15
    int tid = threadIdx.x;
    int m = tid >> 5, lane = tid & 31;
    int tap = c >> 4, icc = c & 15;
    uint32_t words[4];
#pragma unroll
    for (int pair = 0; pair < 4; pair++) {
        int oc = m * 16 + (lane >> 2) + (pair & 1) * 8;
        int kk = (pair >> 1) * 16 + (lane & 3) * 4;
        uint32_t wd = 0;
#pragma unroll
        for (int j = 0; j < 4; j++) {
            int s = icc * 32 + kk + j;                          // GEMM k slot (shuffled order)
            int icw = (s < 256) ? (2 * s) : (2 * (s - 256) + 1); // original w2 channel
            float v = w2[((size_t)(oc * 512 + icw)) * 9 + tap];
            wd |= (uint32_t)(uint8_t)(int8_t)(v >= 0.f ? 1 : -1) << (8 * j);
        }
        words[pair] = wd;
    }
    *(uint4*)(g_A2p + ((size_t)(c * 16 + m) * 32 + lane) * 16) =
        make_uint4(words[0], words[1], words[2], words[3]);
}

// ---------------- zero borders of padded act tensors ----------------
__global__ void zero_pads() {
    int cell = blockIdx.x * blockDim.x + threadIdx.x;
    if (cell >= BATCH * 58 * 58) return;
    int r = cell % (58 * 58);
    int yy = r / 58, xx = r % 58;
    if (yy == 0 || yy == 57 || xx == 0 || xx == 57) {
        uint4 z = make_uint4(0, 0, 0, 0);
        uint4* p1 = (uint4*)(g_acts1 + (size_t)cell * 256);
#pragma unroll
        for (int i = 0; i < 16; i++) p1[i] = z;
        uint4* p2 = (uint4*)(g_acts2 + (size_t)cell * 512);
#pragma unroll
        for (int i = 0; i < 32; i++) p2[i] = z;
    }
}

// ---------------- activation pack (transposed via smem) ----------------
__global__ __launch_bounds__(256) void pack_acts(const float* __restrict__ x,
                                                 const float* __restrict__ mb) {
    __shared__ float T[64][65];
    int blk = blockIdx.x;           // 0..783
    int b = blk / 49, tile = blk % 49;
    int p0 = tile * 64;
    int tid = threadIdx.x;
#pragma unroll 1
    for (int half = 0; half < 2; half++) {
#pragma unroll 1
        for (int icc = 0; icc < 4; icc++) {
            int ic0 = half * 256 + icc * 64;
            for (int e = tid; e < 4096; e += 256) {
                int ic_l = e >> 6, px = e & 63;
                float v = x[((size_t)b * 512 + ic0 + ic_l) * NPIX + p0 + px];
                if (half) v += __ldg(&mb[icc * 64 + ic_l]);
                T[px][ic_l] = v;
            }
            __syncthreads();
            float* dstF = half ? g_idleb : g_xact;
            for (int e = tid; e < 4096; e += 256) {
                int px = e >> 6, ic_l = e & 63;
                dstF[((size_t)b * NPIX + p0 + px) * 256 + icc * 64 + ic_l] = T[px][ic_l];
            }
            for (int e = tid; e < 1024; e += 256) {
                int px = e >> 4, w4 = e & 15;
                uint32_t wd = 0;
#pragma unroll
                for (int j = 0; j < 4; j++) {
                    float v = T[px][w4 * 4 + j];
                    wd |= (uint32_t)(uint8_t)(int8_t)(v >= 0.f ? 1 : -1) << (8 * j);
                }
                int p = p0 + px;
                int y = p / WW, xx2 = p % WW;
                size_t pb = ((size_t)(b * 58 + y + 1) * 58 + (xx2 + 1));
                if (half == 0)
                    *(uint32_t*)(g_acts1 + pb * 256 + icc * 64 + w4 * 4) = wd;
                else
                    *(uint32_t*)(g_acts2 + pb * 512 + 256 + icc * 64 + w4 * 4) = wd;
            }
            __syncthreads();
        }
    }
}

// ---------------- IMMA implicit-GEMM conv ----------------
// CTA: M=256 oc x N=64 px; 8 warps, warp tile 64 oc x 32 px.
// k chunks of 32 (one tap x 32 ic). mma.sync.m16n8k32.s8 (exact +-1 arithmetic).
template <int STAGE>
__global__ __launch_bounds__(256, 2) void conv_imma(float* __restrict__ out) {
    constexpr int IC = (STAGE == 1) ? 256 : 512;
    constexpr int NCH = 9 * (IC / 32);
    extern __shared__ char smem[];
    // mainloop: A buf: [buf*8192, +8192); B buf: 16384 + buf*3072 ([64 px][48B])
    // epilogue: alpha [0,1024), cc [1024,2048), Vs floats at 2048, row stride 261

    const int8_t* Ap = (STAGE == 1) ? g_A1p : g_A2p;
    const int8_t* Pacts = (STAGE == 1) ? g_acts1 : g_acts2;

    int tile = blockIdx.x, b = blockIdx.y;
    int p0 = tile * 64;
    int tid = threadIdx.x, wid = tid >> 5, lane = tid & 31;
    int g = lane >> 2, q = lane & 3;
    int mbase16 = (wid >> 1) * 4;       // m-frag base (4 frags = 64 oc)
    int nbase = (wid & 1) * 32;         // px base within tile

    // B loader assignment
    int px_b = tid >> 1, halfsel = tid & 1;
    int pb_ = p0 + px_b;
    int yb = pb_ / WW, xb = pb_ % WW;
    size_t baseB = ((size_t)(b * 58 + yb) * 58 + xb) * IC + halfsel * 16;

    int acc[4][4][4];
#pragma unroll
    for (int mi = 0; mi < 4; mi++)
#pragma unroll
        for (int ni = 0; ni < 4; ni++)
#pragma unroll
            for (int r = 0; r < 4; r++) acc[mi][ni][r] = 0;

    uint4 ra0, ra1, rb;
    // prologue: chunk 0
    {
        const uint4* Asrc = (const uint4*)(Ap + (size_t)0 * 8192 + tid * 32);
        ra0 = Asrc[0]; ra1 = Asrc[1];
        if (tid < 128) rb = *(const uint4*)(Pacts + baseB + (0 * 58 + 0) * IC + 0);
        uint4* Adst = (uint4*)(smem + tid * 32);
        Adst[0] = ra0; Adst[1] = ra1;
        if (tid < 128) *(uint4*)(smem + 16384 + px_b * 48 + halfsel * 16) = rb;
    }
    __syncthreads();

#pragma unroll 1
    for (int c = 0; c < NCH; c++) {
        int buf = c & 1;
        if (c + 1 < NCH) {
            int cn = c + 1;
            const uint4* Asrc = (const uint4*)(Ap + (size_t)cn * 8192 + tid * 32);
            ra0 = Asrc[0]; ra1 = Asrc[1];
            if (tid < 128) {
                int tap = cn / (IC / 32), icc = cn % (IC / 32);
                int dy = tap / 3, dx = tap % 3;
                rb = *(const uint4*)(Pacts + baseB + (size_t)(dy * 58 + dx) * IC + icc * 32);
            }
        }
        // compute chunk c
        uint32_t afr[4][4], bfr[4][2];
#pragma unroll
        for (int mi = 0; mi < 4; mi++) {
            uint4 v = *(const uint4*)(smem + buf * 8192 + ((mbase16 + mi) * 32 + lane) * 16);
            afr[mi][0] = v.x; afr[mi][1] = v.y; afr[mi][2] = v.z; afr[mi][3] = v.w;
        }
#pragma unroll
        for (int ni = 0; ni < 4; ni++) {
            const char* bp = smem + 16384 + buf * 3072 + (nbase + ni * 8 + g) * 48 + q * 4;
            bfr[ni][0] = *(const uint32_t*)(bp);
            bfr[ni][1] = *(const uint32_t*)(bp + 16);
        }
#pragma unroll
        for (int mi = 0; mi < 4; mi++)
#pragma unroll
            for (int ni = 0; ni < 4; ni++) {
                asm volatile(
                    "mma.sync.aligned.m16n8k32.row.col.s32.s8.s8.s32 "
                    "{%0,%1,%2,%3}, {%4,%5,%6,%7}, {%8,%9}, {%0,%1,%2,%3};\n"
                    : "+r"(acc[mi][ni][0]), "+r"(acc[mi][ni][1]),
                      "+r"(acc[mi][ni][2]), "+r"(acc[mi][ni][3])
                    : "r"(afr[mi][0]), "r"(afr[mi][1]), "r"(afr[mi][2]), "r"(afr[mi][3]),
                      "r"(bfr[ni][0]), "r"(bfr[ni][1]));
            }
        __syncthreads();
        if (c + 1 < NCH) {
            int bn = (c + 1) & 1;
            uint4* Adst = (uint4*)(smem + bn * 8192 + tid * 32);
            Adst[0] = ra0; Adst[1] = ra1;
            if (tid < 128) *(uint4*)(smem + 16384 + bn * 3072 + px_b * 48 + halfsel * 16) = rb;
        }
        __syncthreads();
    }

    // ---------------- epilogue ----------------
    float* alphaS = (float*)smem;
    float* ccS = alphaS + 256;
    float* Vs = (float*)(smem + 2048);          // [64 px][261]
    const float* Aal = (STAGE == 1) ? g_alpha1 : g_alpha2;
    const float* Acc = (STAGE == 1) ? g_c1 : g_c2;
    alphaS[tid] = __ldg(&Aal[tid]);
    ccS[tid] = __ldg(&Acc[tid]);
    // preload residual tile
    if (STAGE == 1) {
        for (int e = tid; e < 64 * 256; e += 256) {
            int px = e >> 8, icx = e & 255;
            Vs[px * 261 + icx] = __ldg(&g_xact[((size_t)b * NPIX + p0 + px) * 256 + icx]);
        }
    } else {
        for (int e = tid; e < 64 * 128; e += 256) {
            int px = e >> 7, j = e & 127;
            size_t ppx = (size_t)b * NPIX + p0 + px;
            Vs[px * 261 + 2 * j] = __ldg(&g_out1f[ppx * 128 + j]);
            Vs[px * 261 + 2 * j + 1] = __ldg(&g_idleb[ppx * 256 + j]);
        }
    }
    __syncthreads();
    // BN + residual + clip from accumulators
#pragma unroll
    for (int mi = 0; mi < 4; mi++)
#pragma unroll
        for (int ni = 0; ni < 4; ni++)
#pragma unroll
            for (int r = 0; r < 4; r++) {
                int oc = mbase16 * 16 + mi * 16 + g + (r >> 1) * 8;
                int px = nbase + ni * 8 + q * 2 + (r & 1);
                float val = (float)acc[mi][ni][r] * alphaS[oc] + ccS[oc] + Vs[px * 261 + oc];
                val = fminf(fmaxf(val, -1.f), 1.f);
                Vs[px * 261 + oc] = val;
            }
    __syncthreads();
    // writeout
    if (STAGE == 1) {
        for (int e = tid; e < 4096; e += 256) {       // s8 signs -> acts2 slots 0..255 (ALL 256 ch)
            int px = e >> 6, w64 = e & 63;
            uint32_t wd = 0;
#pragma unroll
            for (int j = 0; j < 4; j++) {
                float v = Vs[px * 261 + w64 * 4 + j];
                wd |= (uint32_t)(uint8_t)(int8_t)(v >= 0.f ? 1 : -1) << (8 * j);
            }
            int p = p0 + px;
            int y = p / WW, xx2 = p % WW;
            size_t pb = ((size_t)(b * 58 + y + 1) * 58 + (xx2 + 1));
            *(uint32_t*)(g_acts2 + pb * 512 + w64 * 4) = wd;
        }
        for (int e = tid; e < 64 * 128; e += 256) {   // float out1 (oc<128) for stage2 residual
            int px = e >> 7, j = e & 127;
            g_out1f[((size_t)b * NPIX + p0 + px) * 128 + j] = Vs[px * 261 + j];
        }
    } else {
        for (int e = tid; e < 64 * 256; e += 256) {   // final NCHW output
            int oc = e >> 6, px = e & 63;
            out[((size_t)(b * 256 + oc)) * NPIX + p0 + px] = Vs[px * 261 + oc];
        }
    }
}

// ---------------- launch ----------------
extern "C" void kernel_launch(void* const* d_in, const int* in_sizes, int n_in,
                              void* d_out, int out_size) {
    const float* x      = (const float*)d_in[0];
    const float* w1     = (const float*)d_in[1];
    const float* w2     = (const float*)d_in[2];
    const float* gamma1 = (const float*)d_in[3];
    const float* beta1  = (const float*)d_in[4];
    const float* mean1  = (const float*)d_in[5];
    const float* var1   = (const float*)d_in[6];
    const float* gamma2 = (const float*)d_in[7];
    const float* beta2  = (const float*)d_in[8];
    const float* mean2  = (const float*)d_in[9];
    const float* var2   = (const float*)d_in[10];
    const float* mb     = (const float*)d_in[11];
    float* out = (float*)d_out;

    const int SMEM = 2048 + 64 * 261 * 4;   // 68864 B (epilogue is the max)
    cudaFuncSetAttribute(conv_imma<1>, cudaFuncAttributeMaxDynamicSharedMemorySize, SMEM);
    cudaFuncSetAttribute(conv_imma<2>, cudaFuncAttributeMaxDynamicSharedMemorySize, SMEM);

    prep_bn1<<<256, 256>>>(w1, gamma1, beta1, mean1, var1);
    prep_bn2<<<256, 256>>>(w2, gamma2, beta2, mean2, var2);
    pack_w1<<<72, 512>>>(w1);
    pack_w2<<<144, 512>>>(w2);
    zero_pads<<<(BATCH * 58 * 58 + 255) / 256, 256>>>();
    pack_acts<<<784, 256>>>(x, mb);

    dim3 grid(49, BATCH);
    conv_imma<1><<<grid, 256, SMEM>>>(out);
    conv_imma<2><<<grid, 256, SMEM>>>(out);
}

// round 11
// speedup vs baseline: 2.4241x; 2.4241x over previous
#include <cuda_runtime.h>
#include <cstdint>

#define BATCH 16
#define HH 56
#define WW 56
#define EPSV 1e-5f

// ---------------- scratch (device globals; no allocation) ----------------
__device__ uint32_t g_Abits[BATCH * 8 * HH * WW];    // stage1 input bits  [b][w][y][x]
__device__ uint32_t g_Sbits[BATCH * 16 * HH * WW];   // stage2 input bits  [b][w][y][x]
__device__ float    g_Out1f[BATCH * 128 * HH * WW];  // out1 channels 0..127
__device__ uint32_t g_W1b[72 * 256];                 // [k][oc]
__device__ uint32_t g_W2b[144 * 256];                // permuted for shuffle
__device__ int      g_NW1[9 * 256];
__device__ int      g_NW2[9 * 256];
__device__ float    g_alpha1[256], g_c1[256], g_alpha2[256], g_c2[256];

// ---------------- weight prep ----------------
__global__ void prep_w1(const float* __restrict__ w1, const float* __restrict__ gm,
                        const float* __restrict__ bt, const float* __restrict__ mn,
                        const float* __restrict__ vr) {
    int oc = blockIdx.x;
    int c  = threadIdx.x;
    int lane = c & 31, wi = c >> 5;
    __shared__ int nw[9];
    __shared__ float red[8];
    if (c < 9) nw[c] = 0;
    __syncthreads();
    float asum = 0.f;
#pragma unroll
    for (int r = 0; r < 3; r++)
#pragma unroll
        for (int dx = 0; dx < 3; dx++) {
            float v = w1[((oc * 256 + c) * 3 + r) * 3 + dx];
            asum += fabsf(v);
            unsigned word = __ballot_sync(0xffffffffu, v < 0.f);
            if (lane == 0) {
                int k = (wi * 3 + r) * 3 + dx;
                g_W1b[k * 256 + oc] = word;
                atomicAdd(&nw[r * 3 + dx], __popc(word));
            }
        }
    __syncthreads();
    if (c < 9) g_NW1[c * 256 + oc] = nw[c];
    for (int o = 16; o > 0; o >>= 1) asum += __shfl_xor_sync(0xffffffffu, asum, o);
    if (lane == 0) red[wi] = asum;
    __syncthreads();
    if (c == 0) {
        float s = 0.f;
#pragma unroll
        for (int i = 0; i < 8; i++) s += red[i];
        float scale = s / (256.f * 9.f);
        float inv = gm[oc] / sqrtf(vr[oc] + EPSV);
        g_alpha1[oc] = scale * inv;
        g_c1[oc] = bt[oc] - mn[oc] * inv;
    }
}

__global__ void prep_w2(const float* __restrict__ w2, const float* __restrict__ gm,
                        const float* __restrict__ bt, const float* __restrict__ mn,
                        const float* __restrict__ vr) {
    int oc = blockIdx.x;
    int c  = threadIdx.x;
    int lane = c & 31;
    __shared__ int nw[9];
    __shared__ float red[8];
    if (c < 9) nw[c] = 0;
    __syncthreads();
    float asum = 0.f;
    for (int it = 0; it < 2; it++) {
        int j  = it * 256 + c;
        int ic = (j < 256) ? (2 * j) : (2 * (j - 256) + 1);
        int wi = j >> 5;
#pragma unroll
        for (int r = 0; r < 3; r++)
#pragma unroll
            for (int dx = 0; dx < 3; dx++) {
                float v = w2[((oc * 512 + ic) * 3 + r) * 3 + dx];
                asum += fabsf(v);
                unsigned word = __ballot_sync(0xffffffffu, v < 0.f);
                if (lane == 0) {
                    int k = (wi * 3 + r) * 3 + dx;
                    g_W2b[k * 256 + oc] = word;
                    atomicAdd(&nw[r * 3 + dx], __popc(word));
                }
            }
    }
    __syncthreads();
    if (c < 9) g_NW2[c * 256 + oc] = nw[c];
    for (int o = 16; o > 0; o >>= 1) asum += __shfl_xor_sync(0xffffffffu, asum, o);
    if (lane == 0) red[c >> 5] = asum;
    __syncthreads();
    if (c == 0) {
        float s = 0.f;
#pragma unroll
        for (int i = 0; i < 8; i++) s += red[i];
        float scale = s / (512.f * 9.f);
        float inv = gm[oc] / sqrtf(vr[oc] + EPSV);
        g_alpha2[oc] = scale * inv;
        g_c2[oc] = bt[oc] - mn[oc] * inv;
    }
}

// ---------------- input packing ----------------
__global__ void pack_input(const float* __restrict__ x, const float* __restrict__ mb) {
    int n = blockIdx.x * blockDim.x + threadIdx.x;
    if (n >= BATCH * HH * WW) return;
    int xw = n % (HH * WW);
    int b  = n / (HH * WW);
    const float* xp = x + (size_t)b * 512 * HH * WW + xw;
#pragma unroll 1
    for (int wi = 0; wi < 8; wi++) {
        uint32_t word = 0;
#pragma unroll
        for (int k = 0; k < 32; k++) {
            float v = __ldg(&xp[(size_t)(wi * 32 + k) * HH * WW]);
            word |= (v < 0.f ? 1u : 0u) << k;
        }
        g_Abits[(b * 8 + wi) * HH * WW + xw] = word;
    }
#pragma unroll 1
    for (int wi = 0; wi < 8; wi++) {
        uint32_t word = 0;
#pragma unroll
        for (int k = 0; k < 32; k++) {
            int ci = wi * 32 + k;
            float v = __ldg(&xp[(size_t)(256 + ci) * HH * WW]) + __ldg(&mb[ci]);
            word |= (v < 0.f ? 1u : 0u) << k;
        }
        g_Sbits[(b * 16 + (8 + wi)) * HH * WW + xw] = word;
    }
}

__device__ __forceinline__ uint32_t maj3(uint32_t a, uint32_t b, uint32_t c) {
    return (a & b) | (b & c) | (a & c);   // single LOP3, LUT 0xE8
}
__device__ __forceinline__ uint32_t xor3(uint32_t a, uint32_t b, uint32_t c) {
    return a ^ b ^ c;                      // single LOP3, LUT 0x96
}

// ---------------- binarized conv (XOR + row CSA, packed accs) -------------
// Block: 256 threads; tile = 56 px (one row) x 64 oc. Thread: 7 px x 2 oc.
// CSA: popc(x0)+popc(x1)+popc(x2) = popc(xor3)+2*popc(maj3).
// Packed acc: lo16 = sum popc(xor3), hi16 = sum popc(maj3).
// Both accumulates forced onto the fma pipe (IMAD) via opaque 'one'.
// HALVES=2 (stage2): only half of Ws resident; reloaded once (occupancy 4->5).
template <int WORDS, int STAGE, int MINB, int HALVES>
__global__ __launch_bounds__(256, MINB) void binconv(const float* __restrict__ x,
                                                     const float* __restrict__ mb,
                                                     float* __restrict__ out) {
    constexpr int CTOT = WORDS * 32;
    constexpr int WPH  = WORDS / HALVES;         // words per half
    constexpr int KRES = WPH * 9;                // k-entries resident in Ws
    extern __shared__ uint32_t smem[];
    uint32_t* Ws = smem;                          // [KRES][64]  (reused post-mainloop)
    uint32_t* As = smem + KRES * 64;              // [WORDS*3][58]
    float*    Rs = (float*)(As + WORDS * 3 * 58); // stage1: [64][57] residual -> Vs
    float*    Vs = (STAGE == 1) ? Rs : (float*)Ws;
    uint32_t* stg = Ws;                           // stage1 sign-bit staging

    const uint32_t* Gb = (STAGE == 1) ? g_Abits : g_Sbits;
    const uint32_t* Wg = (STAGE == 1) ? g_W1b : g_W2b;

    int ocq = blockIdx.x;        // oc quarter (64 oc)
    int y = blockIdx.y;
    int b = blockIdx.z;
    int tid = threadIdx.x;
    int og = tid & 31;           // lane: oc pair index
    int g  = tid >> 5;           // warp: pixel group (7 px)

    uint32_t one = 1u | (blockIdx.z >> 16);   // == 1, opaque to ptxas (keeps IMAD on fma pipe)

    uint32_t acc[7][2];
#pragma unroll
    for (int p = 0; p < 7; p++) { acc[p][0] = 0; acc[p][1] = 0; }

#pragma unroll 1
    for (int half = 0; half < HALVES; half++) {
        if (HALVES > 1 && half > 0) __syncthreads();   // prior-half Ws reads done
        // ---- cooperative loads ----
        for (int idx = tid; idx < KRES * 64; idx += 256) {
            int k = idx >> 6, o = idx & 63;
            Ws[idx] = Wg[(half * KRES + k) * 256 + ocq * 64 + o];
        }
        if (half == 0) {
            for (int idx = tid; idx < WORDS * 3 * 58; idx += 256) {
                int c = idx % 58;
                int wr = idx / 58;
                int r = wr % 3, w = wr / 3;
                int yy = y + r - 1;
                int xx = c - 1;
                uint32_t v = 0;
                if ((unsigned)yy < HH && (unsigned)xx < WW)
                    v = Gb[((b * WORDS + w) * HH + yy) * WW + xx];
                As[wr * 58 + c] = v;
            }
            if (STAGE == 1) {
                for (int idx = tid; idx < 64 * WW; idx += 256) {
                    int oc_l = idx / WW, px = idx % WW;
                    Rs[oc_l * 57 + px] =
                        __ldg(&x[(((size_t)b * 512 + ocq * 64 + oc_l) * HH + y) * WW + px]);
                }
            }
        }
        __syncthreads();

        // ---- main loop (this half) ----
#pragma unroll 2
        for (int wl = 0; wl < WPH; wl++) {
            int w = half * WPH + wl;               // global word index (As)
#pragma unroll
            for (int r = 0; r < 3; r++) {
                const uint32_t* arow = &As[(w * 3 + r) * 58 + 7 * g];
                uint32_t a[9];
#pragma unroll
                for (int i = 0; i < 9; i++) a[i] = arow[i];
                int k0 = (wl * 3 + r) * 3;          // local k index (Ws)
                uint2 w0 = *reinterpret_cast<const uint2*>(&Ws[(k0 + 0) * 64 + og * 2]);
                uint2 w1 = *reinterpret_cast<const uint2*>(&Ws[(k0 + 1) * 64 + og * 2]);
                uint2 w2 = *reinterpret_cast<const uint2*>(&Ws[(k0 + 2) * 64 + og * 2]);
#pragma unroll
                for (int p = 0; p < 7; p++) {
                    {
                        uint32_t x0 = a[p] ^ w0.x, x1 = a[p + 1] ^ w1.x, x2 = a[p + 2] ^ w2.x;
                        uint32_t t = acc[p][0];
                        t = __popc(maj3(x0, x1, x2)) * 65536u + t;   // IMAD (fma pipe)
                        t = __popc(xor3(x0, x1, x2)) * one + t;      // IMAD (fma pipe)
                        acc[p][0] = t;
                    }
                    {
                        uint32_t x0 = a[p] ^ w0.y, x1 = a[p + 1] ^ w1.y, x2 = a[p + 2] ^ w2.y;
                        uint32_t t = acc[p][1];
                        t = __popc(maj3(x0, x1, x2)) * 65536u + t;
                        t = __popc(xor3(x0, x1, x2)) * one + t;
                        acc[p][1] = t;
                    }
                }
            }
        }
    }
    __syncthreads();   // Ws reads done; region reusable

    // ---- epilogue ----
    int ocbase = ocq * 64 + og * 2;
    const float* Ag = (STAGE == 1) ? g_alpha1 : g_alpha2;
    const float* Cg = (STAGE == 1) ? g_c1 : g_c2;
    const int* NWg = (STAGE == 1) ? g_NW1 : g_NW2;
    float alpha[2], cc[2];
#pragma unroll
    for (int j = 0; j < 2; j++) { alpha[j] = __ldg(&Ag[ocbase + j]); cc[j] = __ldg(&Cg[ocbase + j]); }
    bool ybord = (y == 0) || (y == HH - 1);

#pragma unroll
    for (int p = 0; p < 7; p++) {
        int xx = 7 * g + p;
        bool bord = ybord || (xx == 0) || (xx == WW - 1);
        int nv = 9;
        int corr[2] = {0, 0};
        if (bord) {
#pragma unroll
            for (int t = 0; t < 9; t++) {
                int dy = t / 3 - 1, dx = t % 3 - 1;
                if ((unsigned)(y + dy) >= HH || (unsigned)(xx + dx) >= WW) {
                    nv--;
                    corr[0] += __ldg(&NWg[t * 256 + ocbase]);
                    corr[1] += __ldg(&NWg[t * 256 + ocbase + 1]);
                }
            }
        }
        if (STAGE == 1) {
            uint32_t sb = 0;
#pragma unroll
            for (int j = 0; j < 2; j++) {
                uint32_t av = acc[p][j];
                int ones = (int)(av & 0xFFFFu) + 2 * (int)(av >> 16);
                int dot = CTOT * nv - 2 * ones + 2 * corr[j];
                float val = (float)dot * alpha[j] + cc[j];
                val += Rs[(og * 2 + j) * 57 + xx];
                val = fminf(fmaxf(val, -1.f), 1.f);
                Vs[(og * 2 + j) * 57 + xx] = val;
                sb |= (val < 0.f ? 1u : 0u) << j;
            }
            stg[xx * 32 + og] = sb;
        } else {
#pragma unroll
            for (int j = 0; j < 2; j++) {
                uint32_t av = acc[p][j];
                int ones = (int)(av & 0xFFFFu) + 2 * (int)(av >> 16);
                int dot = CTOT * nv - 2 * ones + 2 * corr[j];
                Vs[(og * 2 + j) * 57 + xx] = (float)dot * alpha[j] + cc[j];
            }
        }
    }
    __syncthreads();

    // ---- coalesced writeout ----
    if (STAGE == 1) {
        if (ocq < 2) {
            for (int idx = tid; idx < 64 * WW; idx += 256) {
                int oc_l = idx / WW, px = idx % WW;
                g_Out1f[(((size_t)b * 128 + ocq * 64 + oc_l) * HH + y) * WW + px] =
                    Vs[oc_l * 57 + px];
            }
        }
        if (tid < 2 * WW) {
            int px = tid >> 1, wsel = tid & 1;
            uint32_t word = 0;
#pragma unroll
            for (int q = 0; q < 16; q++) {
                uint32_t v = stg[px * 32 + wsel * 16 + q];
                word |= (v & 1u) << (2 * q);
                word |= ((v >> 1) & 1u) << (2 * q + 1);
            }
            g_Sbits[((b * 16 + (ocq * 2 + wsel)) * HH + y) * WW + px] = word;
        }
    } else {
        for (int idx = tid; idx < 64 * WW; idx += 256) {
            int oc_l = idx / WW, px = idx % WW;
            int oc = ocq * 64 + oc_l;
            float v = Vs[oc_l * 57 + px];
            float res;
            if ((oc & 1) == 0)
                res = __ldg(&g_Out1f[(((size_t)b * 128 + (oc >> 1)) * HH + y) * WW + px]);
            else
                res = __ldg(&x[(((size_t)b * 512 + 256 + (oc >> 1)) * HH + y) * WW + px]) +
                      __ldg(&mb[oc >> 1]);
            v = fminf(fmaxf(v + res, -1.f), 1.f);
            out[(((size_t)b * 256 + oc) * HH + y) * WW + px] = v;
        }
    }
}

// ---------------- launch ----------------
extern "C" void kernel_launch(void* const* d_in, const int* in_sizes, int n_in,
                              void* d_out, int out_size) {
    const float* x      = (const float*)d_in[0];
    const float* w1     = (const float*)d_in[1];
    const float* w2     = (const float*)d_in[2];
    const float* gamma1 = (const float*)d_in[3];
    const float* beta1  = (const float*)d_in[4];
    const float* mean1  = (const float*)d_in[5];
    const float* var1   = (const float*)d_in[6];
    const float* gamma2 = (const float*)d_in[7];
    const float* beta2  = (const float*)d_in[8];
    const float* mean2  = (const float*)d_in[9];
    const float* var2   = (const float*)d_in[10];
    const float* mb     = (const float*)d_in[11];
    float* out = (float*)d_out;

    // stage1: Ws 72*64 + As 8*3*58 + Rs 64*57  = 38592 B  -> 5 CTAs/SM
    // stage2: Ws 72*64 + As 16*3*58            = 29568 B  -> 5 CTAs/SM (reg-capped)
    const int smem1 = (72 * 64 + 8 * 3 * 58 + 64 * 57) * 4;
    const int smem2 = (72 * 64 + 16 * 3 * 58) * 4;
    cudaFuncSetAttribute(binconv<8, 1, 5, 1>,  cudaFuncAttributeMaxDynamicSharedMemorySize, smem1);
    cudaFuncSetAttribute(binconv<16, 2, 5, 2>, cudaFuncAttributeMaxDynamicSharedMemorySize, smem2);

    prep_w1<<<256, 256>>>(w1, gamma1, beta1, mean1, var1);
    prep_w2<<<256, 256>>>(w2, gamma2, beta2, mean2, var2);
    pack_input<<<(BATCH * HH * WW + 255) / 256, 256>>>(x, mb);

    dim3 grid(4, HH, BATCH);
    binconv<8, 1, 5, 1><<<grid, 256, smem1>>>(x, mb, out);
    binconv<16, 2, 5, 2><<<grid, 256, smem2>>>(x, mb, out);
}

// round 12
// speedup vs baseline: 2.4699x; 1.0189x over previous
#include <cuda_runtime.h>
#include <cstdint>

#define BATCH 16
#define HH 56
#define WW 56
#define NPIX (HH * WW)
#define EPSV 1e-5f

// ---------------- scratch (device globals; no allocation) ----------------
__device__ uint32_t g_Abits[BATCH * 8 * HH * WW];    // stage1 input bits  [b][w][y][x]
__device__ uint32_t g_Sbits[BATCH * 16 * HH * WW];   // stage2 input bits  [b][w][y][x]
__device__ float    g_Out1f[BATCH * 128 * HH * WW];  // out1 channels 0..127
__device__ uint32_t g_W1b[72 * 256];                 // [k][oc]
__device__ uint32_t g_W2b[144 * 256];                // permuted for shuffle
__device__ int      g_NW1[9 * 256];
__device__ int      g_NW2[9 * 256];
__device__ float    g_alpha1[256], g_c1[256], g_alpha2[256], g_c2[256];

// ---------------- weight prep ----------------
__global__ void prep_w1(const float* __restrict__ w1, const float* __restrict__ gm,
                        const float* __restrict__ bt, const float* __restrict__ mn,
                        const float* __restrict__ vr) {
    int oc = blockIdx.x;
    int c  = threadIdx.x;
    int lane = c & 31, wi = c >> 5;
    __shared__ int nw[9];
    __shared__ float red[8];
    if (c < 9) nw[c] = 0;
    __syncthreads();
    float asum = 0.f;
#pragma unroll
    for (int r = 0; r < 3; r++)
#pragma unroll
        for (int dx = 0; dx < 3; dx++) {
            float v = w1[((oc * 256 + c) * 3 + r) * 3 + dx];
            asum += fabsf(v);
            unsigned word = __ballot_sync(0xffffffffu, v < 0.f);
            if (lane == 0) {
                int k = (wi * 3 + r) * 3 + dx;
                g_W1b[k * 256 + oc] = word;
                atomicAdd(&nw[r * 3 + dx], __popc(word));
            }
        }
    __syncthreads();
    if (c < 9) g_NW1[c * 256 + oc] = nw[c];
    for (int o = 16; o > 0; o >>= 1) asum += __shfl_xor_sync(0xffffffffu, asum, o);
    if (lane == 0) red[wi] = asum;
    __syncthreads();
    if (c == 0) {
        float s = 0.f;
#pragma unroll
        for (int i = 0; i < 8; i++) s += red[i];
        float scale = s / (256.f * 9.f);
        float inv = gm[oc] / sqrtf(vr[oc] + EPSV);
        g_alpha1[oc] = scale * inv;
        g_c1[oc] = bt[oc] - mn[oc] * inv;
    }
}

__global__ void prep_w2(const float* __restrict__ w2, const float* __restrict__ gm,
                        const float* __restrict__ bt, const float* __restrict__ mn,
                        const float* __restrict__ vr) {
    int oc = blockIdx.x;
    int c  = threadIdx.x;
    int lane = c & 31;
    __shared__ int nw[9];
    __shared__ float red[8];
    if (c < 9) nw[c] = 0;
    __syncthreads();
    float asum = 0.f;
    for (int it = 0; it < 2; it++) {
        int j  = it * 256 + c;
        int ic = (j < 256) ? (2 * j) : (2 * (j - 256) + 1);
        int wi = j >> 5;
#pragma unroll
        for (int r = 0; r < 3; r++)
#pragma unroll
            for (int dx = 0; dx < 3; dx++) {
                float v = w2[((oc * 512 + ic) * 3 + r) * 3 + dx];
                asum += fabsf(v);
                unsigned word = __ballot_sync(0xffffffffu, v < 0.f);
                if (lane == 0) {
                    int k = (wi * 3 + r) * 3 + dx;
                    g_W2b[k * 256 + oc] = word;
                    atomicAdd(&nw[r * 3 + dx], __popc(word));
                }
            }
    }
    __syncthreads();
    if (c < 9) g_NW2[c * 256 + oc] = nw[c];
    for (int o = 16; o > 0; o >>= 1) asum += __shfl_xor_sync(0xffffffffu, asum, o);
    if (lane == 0) red[c >> 5] = asum;
    __syncthreads();
    if (c == 0) {
        float s = 0.f;
#pragma unroll
        for (int i = 0; i < 8; i++) s += red[i];
        float scale = s / (512.f * 9.f);
        float inv = gm[oc] / sqrtf(vr[oc] + EPSV);
        g_alpha2[oc] = scale * inv;
        g_c2[oc] = bt[oc] - mn[oc] * inv;
    }
}

// ---------------- input packing (word-parallel: 1 thread = 1 output word) --
// n = (b*16 + wi)*NPIX + xw; warp spans 32 consecutive xw -> all 32 channel
// loads coalesced; 32 independent loads per thread (full MLP).
__global__ __launch_bounds__(256) void pack_input(const float* __restrict__ x,
                                                  const float* __restrict__ mb) {
    int n = blockIdx.x * blockDim.x + threadIdx.x;
    if (n >= BATCH * 16 * NPIX) return;
    int xw = n % NPIX;
    int t  = n / NPIX;
    int wi = t & 15;
    int b  = t >> 4;
    if (wi < 8) {
        const float* xp = x + ((size_t)b * 512 + wi * 32) * NPIX + xw;
        uint32_t word = 0;
#pragma unroll
        for (int k = 0; k < 32; k++) {
            float v = __ldg(&xp[(size_t)k * NPIX]);
            word |= (v < 0.f ? 1u : 0u) << k;
        }
        g_Abits[(b * 8 + wi) * NPIX + xw] = word;
    } else {
        int w2 = wi - 8;
        const float* xp = x + ((size_t)b * 512 + 256 + w2 * 32) * NPIX + xw;
        uint32_t word = 0;
#pragma unroll
        for (int k = 0; k < 32; k++) {
            float v = __ldg(&xp[(size_t)k * NPIX]) + __ldg(&mb[w2 * 32 + k]);
            word |= (v < 0.f ? 1u : 0u) << k;
        }
        g_Sbits[(b * 16 + 8 + w2) * NPIX + xw] = word;
    }
}

__device__ __forceinline__ uint32_t maj3(uint32_t a, uint32_t b, uint32_t c) {
    return (a & b) | (b & c) | (a & c);   // single LOP3, LUT 0xE8
}
__device__ __forceinline__ uint32_t xor3(uint32_t a, uint32_t b, uint32_t c) {
    return a ^ b ^ c;                      // single LOP3, LUT 0x96
}

// ---------------- binarized conv (XOR + row CSA, packed accs) -------------
// Block: 256 threads; tile = 56 px (one row) x 64 oc. Thread: 7 px x 2 oc.
// CSA: popc(x0)+popc(x1)+popc(x2) = popc(xor3)+2*popc(maj3).
// Packed acc: lo16 = sum popc(xor3), hi16 = sum popc(maj3).
// HALVES=2 (stage2): only half of Ws resident; reloaded once.
template <int WORDS, int STAGE, int MINB, int HALVES>
__global__ __launch_bounds__(256, MINB) void binconv(const float* __restrict__ x,
                                                     const float* __restrict__ mb,
                                                     float* __restrict__ out) {
    constexpr int CTOT = WORDS * 32;
    constexpr int WPH  = WORDS / HALVES;         // words per half
    constexpr int KRES = WPH * 9;                // k-entries resident in Ws
    extern __shared__ uint32_t smem[];
    uint32_t* Ws = smem;                          // [KRES][64]  (reused post-mainloop)
    uint32_t* As = smem + KRES * 64;              // [WORDS*3][58]
    float*    Rs = (float*)(As + WORDS * 3 * 58); // stage1: [64][57] residual -> Vs
    float*    Vs = (STAGE == 1) ? Rs : (float*)Ws;
    uint32_t* stg = Ws;                           // stage1 sign-bit staging

    const uint32_t* Gb = (STAGE == 1) ? g_Abits : g_Sbits;
    const uint32_t* Wg = (STAGE == 1) ? g_W1b : g_W2b;

    int ocq = blockIdx.x;        // oc quarter (64 oc)
    int y = blockIdx.y;
    int b = blockIdx.z;
    int tid = threadIdx.x;
    int og = tid & 31;           // lane: oc pair index
    int g  = tid >> 5;           // warp: pixel group (7 px)

    uint32_t acc[7][2];
#pragma unroll
    for (int p = 0; p < 7; p++) { acc[p][0] = 0; acc[p][1] = 0; }

#pragma unroll 1
    for (int half = 0; half < HALVES; half++) {
        if (HALVES > 1 && half > 0) __syncthreads();   // prior-half Ws reads done
        // ---- cooperative loads ----
        for (int idx = tid; idx < KRES * 64; idx += 256) {
            int k = idx >> 6, o = idx & 63;
            Ws[idx] = Wg[(half * KRES + k) * 256 + ocq * 64 + o];
        }
        if (half == 0) {
            for (int idx = tid; idx < WORDS * 3 * 58; idx += 256) {
                int c = idx % 58;
                int wr = idx / 58;
                int r = wr % 3, w = wr / 3;
                int yy = y + r - 1;
                int xx = c - 1;
                uint32_t v = 0;
                if ((unsigned)yy < HH && (unsigned)xx < WW)
                    v = Gb[((b * WORDS + w) * HH + yy) * WW + xx];
                As[wr * 58 + c] = v;
            }
            if (STAGE == 1) {
                for (int idx = tid; idx < 64 * WW; idx += 256) {
                    int oc_l = idx / WW, px = idx % WW;
                    Rs[oc_l * 57 + px] =
                        __ldg(&x[(((size_t)b * 512 + ocq * 64 + oc_l) * HH + y) * WW + px]);
                }
            }
        }
        __syncthreads();

        // ---- main loop (this half) ----
#pragma unroll 2
        for (int wl = 0; wl < WPH; wl++) {
            int w = half * WPH + wl;               // global word index (As)
#pragma unroll
            for (int r = 0; r < 3; r++) {
                const uint32_t* arow = &As[(w * 3 + r) * 58 + 7 * g];
                uint32_t a[9];
#pragma unroll
                for (int i = 0; i < 9; i++) a[i] = arow[i];
                int k0 = (wl * 3 + r) * 3;          // local k index (Ws)
                uint2 w0 = *reinterpret_cast<const uint2*>(&Ws[(k0 + 0) * 64 + og * 2]);
                uint2 w1 = *reinterpret_cast<const uint2*>(&Ws[(k0 + 1) * 64 + og * 2]);
                uint2 w2 = *reinterpret_cast<const uint2*>(&Ws[(k0 + 2) * 64 + og * 2]);
#pragma unroll
                for (int p = 0; p < 7; p++) {
                    {
                        uint32_t x0 = a[p] ^ w0.x, x1 = a[p + 1] ^ w1.x, x2 = a[p + 2] ^ w2.x;
                        uint32_t t = acc[p][0];
                        t = __popc(maj3(x0, x1, x2)) * 65536u + t;   // IMAD (fma pipe)
                        t += __popc(xor3(x0, x1, x2));               // IADD (alu)
                        acc[p][0] = t;
                    }
                    {
                        uint32_t x0 = a[p] ^ w0.y, x1 = a[p + 1] ^ w1.y, x2 = a[p + 2] ^ w2.y;
                        uint32_t t = acc[p][1];
                        t = __popc(maj3(x0, x1, x2)) * 65536u + t;
                        t += __popc(xor3(x0, x1, x2));
                        acc[p][1] = t;
                    }
                }
            }
        }
    }
    __syncthreads();   // Ws reads done; region reusable

    // ---- epilogue ----
    int ocbase = ocq * 64 + og * 2;
    const float* Ag = (STAGE == 1) ? g_alpha1 : g_alpha2;
    const float* Cg = (STAGE == 1) ? g_c1 : g_c2;
    const int* NWg = (STAGE == 1) ? g_NW1 : g_NW2;
    float alpha[2], cc[2];
#pragma unroll
    for (int j = 0; j < 2; j++) { alpha[j] = __ldg(&Ag[ocbase + j]); cc[j] = __ldg(&Cg[ocbase + j]); }
    bool ybord = (y == 0) || (y == HH - 1);

#pragma unroll
    for (int p = 0; p < 7; p++) {
        int xx = 7 * g + p;
        bool bord = ybord || (xx == 0) || (xx == WW - 1);
        int nv = 9;
        int corr[2] = {0, 0};
        if (bord) {
#pragma unroll
            for (int t = 0; t < 9; t++) {
                int dy = t / 3 - 1, dx = t % 3 - 1;
                if ((unsigned)(y + dy) >= HH || (unsigned)(xx + dx) >= WW) {
                    nv--;
                    corr[0] += __ldg(&NWg[t * 256 + ocbase]);
                    corr[1] += __ldg(&NWg[t * 256 + ocbase + 1]);
                }
            }
        }
        if (STAGE == 1) {
            uint32_t sb = 0;
#pragma unroll
            for (int j = 0; j < 2; j++) {
                uint32_t av = acc[p][j];
                int ones = (int)(av & 0xFFFFu) + 2 * (int)(av >> 16);
                int dot = CTOT * nv - 2 * ones + 2 * corr[j];
                float val = (float)dot * alpha[j] + cc[j];
                val += Rs[(og * 2 + j) * 57 + xx];
                val = fminf(fmaxf(val, -1.f), 1.f);
                Vs[(og * 2 + j) * 57 + xx] = val;
                sb |= (val < 0.f ? 1u : 0u) << j;
            }
            stg[xx * 32 + og] = sb;
        } else {
#pragma unroll
            for (int j = 0; j < 2; j++) {
                uint32_t av = acc[p][j];
                int ones = (int)(av & 0xFFFFu) + 2 * (int)(av >> 16);
                int dot = CTOT * nv - 2 * ones + 2 * corr[j];
                Vs[(og * 2 + j) * 57 + xx] = (float)dot * alpha[j] + cc[j];
            }
        }
    }
    __syncthreads();

    // ---- coalesced writeout ----
    if (STAGE == 1) {
        if (ocq < 2) {
            for (int idx = tid; idx < 64 * WW; idx += 256) {
                int oc_l = idx / WW, px = idx % WW;
                g_Out1f[(((size_t)b * 128 + ocq * 64 + oc_l) * HH + y) * WW + px] =
                    Vs[oc_l * 57 + px];
            }
        }
        if (tid < 2 * WW) {
            int px = tid >> 1, wsel = tid & 1;
            uint32_t word = 0;
#pragma unroll
            for (int q = 0; q < 16; q++) {
                uint32_t v = stg[px * 32 + wsel * 16 + q];
                word |= (v & 1u) << (2 * q);
                word |= ((v >> 1) & 1u) << (2 * q + 1);
            }
            g_Sbits[((b * 16 + (ocq * 2 + wsel)) * HH + y) * WW + px] = word;
        }
    } else {
        for (int idx = tid; idx < 64 * WW; idx += 256) {
            int oc_l = idx / WW, px = idx % WW;
            int oc = ocq * 64 + oc_l;
            float v = Vs[oc_l * 57 + px];
            float res;
            if ((oc & 1) == 0)
                res = __ldg(&g_Out1f[(((size_t)b * 128 + (oc >> 1)) * HH + y) * WW + px]);
            else
                res = __ldg(&x[(((size_t)b * 512 + 256 + (oc >> 1)) * HH + y) * WW + px]) +
                      __ldg(&mb[oc >> 1]);
            v = fminf(fmaxf(v + res, -1.f), 1.f);
            out[(((size_t)b * 256 + oc) * HH + y) * WW + px] = v;
        }
    }
}

// ---------------- launch ----------------
extern "C" void kernel_launch(void* const* d_in, const int* in_sizes, int n_in,
                              void* d_out, int out_size) {
    const float* x      = (const float*)d_in[0];
    const float* w1     = (const float*)d_in[1];
    const float* w2     = (const float*)d_in[2];
    const float* gamma1 = (const float*)d_in[3];
    const float* beta1  = (const float*)d_in[4];
    const float* mean1  = (const float*)d_in[5];
    const float* var1   = (const float*)d_in[6];
    const float* gamma2 = (const float*)d_in[7];
    const float* beta2  = (const float*)d_in[8];
    const float* mean2  = (const float*)d_in[9];
    const float* var2   = (const float*)d_in[10];
    const float* mb     = (const float*)d_in[11];
    float* out = (float*)d_out;

    const int smem1 = (72 * 64 + 8 * 3 * 58 + 64 * 57) * 4;
    const int smem2 = (72 * 64 + 16 * 3 * 58) * 4;
    cudaFuncSetAttribute(binconv<8, 1, 5, 1>,  cudaFuncAttributeMaxDynamicSharedMemorySize, smem1);
    cudaFuncSetAttribute(binconv<16, 2, 5, 2>, cudaFuncAttributeMaxDynamicSharedMemorySize, smem2);

    prep_w1<<<256, 256>>>(w1, gamma1, beta1, mean1, var1);
    prep_w2<<<256, 256>>>(w2, gamma2, beta2, mean2, var2);
    pack_input<<<(BATCH * 16 * NPIX + 255) / 256, 256>>>(x, mb);

    dim3 grid(4, HH, BATCH);
    binconv<8, 1, 5, 1><<<grid, 256, smem1>>>(x, mb, out);
    binconv<16, 2, 5, 2><<<grid, 256, smem2>>>(x, mb, out);
}